// round 1
// baseline (speedup 1.0000x reference)
#include <cuda_runtime.h>

#define BDIM 4
#define TDIM 300
#define NDIM 200
#define NIN  100
#define KDIM 10

#define BTN (BDIM*TDIM*NDIM)     // 240000
#define BTI (BDIM*TDIM*NIN)      // 120000
#define OUT_TOTAL (NIN*NDIM + NDIM*NDIM + NDIM*KDIM)  // 62000

// scratch (device globals — no cudaMalloc allowed)
__device__ float g_post[BTN];
__device__ float g_pre_rec[BTN];
__device__ float g_pre_out[BTN];
__device__ float g_pre_in[BTI];
__device__ float g_L[BTN];
__device__ float g_G2[BTN];

// ---------------------------------------------------------------------------
// Kernel 1: forward scans + zero output + learning-signal GEMV
//   blocks 0..4  : per-(b,n) scans (refractory/post, pre_rec, pre_out) and
//                  per-(b,i) input trace pre_in
//   blocks 5..   : zero d_out, compute L[b,t,n] = sum_k error1[b,t,k]*w_out[n,k]
// ---------------------------------------------------------------------------
__global__ void k_scan(const float* __restrict__ v, const float* __restrict__ z,
                       const float* __restrict__ x, const float* __restrict__ e1,
                       const float* __restrict__ w_out, float* __restrict__ out) {
    const int tid = threadIdx.x;
    if (blockIdx.x < 5) {
        int idx = blockIdx.x * 256 + tid;
        if (idx < BDIM * NDIM) {
            int b = idx / NDIM, n = idx % NDIM;
            const float* vp = v + b * TDIM * NDIM + n;
            const float* zp = z + b * TDIM * NDIM + n;
            float* postp = g_post    + b * TDIM * NDIM + n;
            float* recp  = g_pre_rec + b * TDIM * NDIM + n;
            float* outp  = g_pre_out + b * TDIM * NDIM + n;
            float pr = 0.f, po = 0.f, zprev = 0.f;
            int c = 0;
            #pragma unroll 4
            for (int t = 0; t < TDIM; t++) {
                float zt = zp[t * NDIM];
                float vt = vp[t * NDIM];
                pr = fmaf(pr, 0.8f, zprev);
                po = fmaf(po, 0.8f, zt);
                // psi = DAMPENING*max(1-|vs|,0)/THRESHOLD = 0.5*max(1-|vs|,0)
                float vs  = (vt - 0.6f) * (1.0f / 0.6f);
                float psi = 0.5f * fmaxf(1.0f - fabsf(vs), 0.0f);
                postp[t * NDIM] = (c > 0) ? 0.0f : psi;
                recp [t * NDIM] = pr;
                outp [t * NDIM] = po;
                c = (zt > 0.f) ? (5 - 1) : ((c > 0) ? (c - 1) : 0);
                zprev = zt;
            }
        } else if (idx < BDIM * NDIM + BDIM * NIN) {
            int j = idx - BDIM * NDIM;
            int b = j / NIN, i = j % NIN;
            const float* xp = x + b * TDIM * NIN + i;
            float* ip = g_pre_in + b * TDIM * NIN + i;
            float a = 0.f;
            #pragma unroll 4
            for (int t = 0; t < TDIM; t++) {
                a = fmaf(a, 0.8f, xp[t * NIN]);
                ip[t * NIN] = a;
            }
        }
    } else {
        int base   = (blockIdx.x - 5) * blockDim.x + tid;
        int stride = (gridDim.x - 5) * blockDim.x;
        for (int i = base; i < OUT_TOTAL; i += stride) out[i] = 0.f;
        for (int i = base; i < BTN; i += stride) {
            int n  = i % NDIM;
            int bt = i / NDIM;
            const float* ep = e1 + bt * KDIM;
            const float* wp = w_out + n * KDIM;
            float a0 = 0.f, a1 = 0.f;
            #pragma unroll
            for (int k = 0; k < KDIM; k += 2) {
                a0 = fmaf(ep[k],     wp[k],     a0);
                a1 = fmaf(ep[k + 1], wp[k + 1], a1);
            }
            g_L[i] = a0 + a1;
        }
    }
}

// ---------------------------------------------------------------------------
// Kernel 2: reverse scan  Lf_t = L_t + 0.8*Lf_{t+1};  G2 = post*(Lf + 0.25*err2)
// grid: (2 n-chunks, 4 batches), 128 threads
// ---------------------------------------------------------------------------
__global__ void k_back(const float* __restrict__ e2) {
    int b = blockIdx.y;
    int n = blockIdx.x * 128 + threadIdx.x;
    if (n >= NDIM) return;
    float c2 = 0.25f * e2[n];                 // REG/(B*T) = 300/1200
    const float* Lp = g_L    + b * TDIM * NDIM + n;
    const float* pp = g_post + b * TDIM * NDIM + n;
    float*       gp = g_G2   + b * TDIM * NDIM + n;
    float lf = 0.f;
    #pragma unroll 4
    for (int t = TDIM - 1; t >= 0; t--) {
        lf = fmaf(lf, 0.8f, Lp[t * NDIM]);
        gp[t * NDIM] = pp[t * NDIM] * (lf + c2);
    }
}

// ---------------------------------------------------------------------------
// Kernel 3: split-K GEMMs, atomicAdd into pre-zeroed output.
//   tiles 0..69 : main GEMM  [pre_in;pre_rec]^T (M=300) x G2 (N=200)
//   tiles 70..76: dw_out GEMM  pre_out^T (M=200) x error1 (N=10)
//   blockIdx.y = K-chunk (b = y>>1, t0 = (y&1)*150)
// ---------------------------------------------------------------------------
__global__ void k_gemm(const float* __restrict__ e1, float* __restrict__ out) {
    __shared__ float As[32][33];
    __shared__ float Bs[32][33];

    const int chunk = blockIdx.y;
    const int b  = chunk >> 1;
    const int t0 = (chunk & 1) * 150;
    const int tile = blockIdx.x;
    const int tid = threadIdx.x;
    const bool is_main = (tile < 70);

    int m0, n0;
    if (is_main) { m0 = (tile / 7) * 32; n0 = (tile % 7) * 32; }
    else         { m0 = (tile - 70) * 32; n0 = 0; }

    const int baseBT = b * TDIM + t0;

    float acc00 = 0.f, acc01 = 0.f, acc10 = 0.f, acc11 = 0.f;
    const int ty = tid >> 4, tx = tid & 15;

    for (int ks = 0; ks < 150; ks += 32) {
        #pragma unroll
        for (int r = 0; r < 4; r++) {
            int e  = tid + r * 256;
            int kk = e >> 5;
            int mm = e & 31;
            int kidx = ks + kk;
            bool kok = (kidx < 150);
            int trow = baseBT + kidx;
            float aval = 0.f, bval = 0.f;
            if (kok) {
                if (is_main) {
                    int gm = m0 + mm;
                    if (gm < NIN)              aval = g_pre_in [trow * NIN  + gm];
                    else if (gm < NIN + NDIM)  aval = g_pre_rec[trow * NDIM + (gm - NIN)];
                    int gn = n0 + mm;
                    if (gn < NDIM)             bval = g_G2[trow * NDIM + gn];
                } else {
                    int gm = m0 + mm;
                    if (gm < NDIM)             aval = g_pre_out[trow * NDIM + gm];
                    if (mm < KDIM)             bval = e1[trow * KDIM + mm];
                }
            }
            As[kk][mm] = aval;
            Bs[kk][mm] = bval;
        }
        __syncthreads();
        #pragma unroll
        for (int kk = 0; kk < 32; kk++) {
            float a0 = As[kk][2 * ty], a1 = As[kk][2 * ty + 1];
            float b0 = Bs[kk][2 * tx], b1 = Bs[kk][2 * tx + 1];
            acc00 = fmaf(a0, b0, acc00);
            acc01 = fmaf(a0, b1, acc01);
            acc10 = fmaf(a1, b0, acc10);
            acc11 = fmaf(a1, b1, acc11);
        }
        __syncthreads();
    }

    float accs[2][2] = {{acc00, acc01}, {acc10, acc11}};
    #pragma unroll
    for (int i = 0; i < 2; i++) {
        #pragma unroll
        for (int j = 0; j < 2; j++) {
            int gm = m0 + 2 * ty + i;
            int gn = n0 + 2 * tx + j;
            float val = accs[i][j];
            if (is_main) {
                if (gn < NDIM) {
                    if (gm < NIN) {
                        atomicAdd(&out[gm * NDIM + gn], val);
                    } else if (gm < NIN + NDIM) {
                        int rr = gm - NIN;
                        if (rr != gn)  // autapse mask: diagonal stays 0
                            atomicAdd(&out[NIN * NDIM + rr * NDIM + gn], val);
                    }
                }
            } else {
                if (gm < NDIM && gn < KDIM)
                    atomicAdd(&out[NIN * NDIM + NDIM * NDIM + gm * KDIM + gn], val);
            }
        }
    }
}

extern "C" void kernel_launch(void* const* d_in, const int* in_sizes, int n_in,
                              void* d_out, int out_size) {
    const float* v     = (const float*)d_in[0];
    const float* z     = (const float*)d_in[1];
    const float* x     = (const float*)d_in[2];
    const float* e1    = (const float*)d_in[3];
    const float* e2    = (const float*)d_in[4];
    const float* w_out = (const float*)d_in[5];
    float* out = (float*)d_out;

    k_scan<<<120, 256>>>(v, z, x, e1, w_out, out);
    k_back<<<dim3(2, 4), 128>>>(e2);
    k_gemm<<<dim3(77, 8), 256>>>(e1, out);
}

// round 2
// speedup vs baseline: 3.5797x; 3.5797x over previous
#include <cuda_runtime.h>

#define BDIM 4
#define TDIM 300
#define NDIM 200
#define NIN  100
#define KDIM 10
#define NCHUNK 10          // ceil(300/32)

#define BTN (BDIM*TDIM*NDIM)     // 240000
#define BTI (BDIM*TDIM*NIN)      // 120000
#define OUT_TOTAL (NIN*NDIM + NDIM*NDIM + NDIM*KDIM)  // 62000

#define D1  0.8f
#define D2  0.64f
#define D4  0.4096f
#define D8  0.16777216f
#define D16 0.0281474976710656f
#define D32 0.000792281625142643f

// scratch (device globals — no cudaMalloc allowed)
__device__ float g_pre_out[BTN];
__device__ float g_pre_in[BTI];
__device__ float g_G2[BTN];

__device__ __forceinline__ float dpow_lane(int l) {
    // d^l for l in [0,31] via exact binary factor product
    float p = 1.f;
    if (l & 1)  p *= D1;
    if (l & 2)  p *= D2;
    if (l & 4)  p *= D4;
    if (l & 8)  p *= D8;
    if (l & 16) p *= D16;
    return p;
}

// ---------------------------------------------------------------------------
// Kernel 1: fully fused traces.
//  blocks  0..27 : (b, n-tile): z/v tiles -> post (ballot window), pre_out
//                  (warp Kogge-Stone scan), L (=e1·w_out^T from smem), reverse
//                  Lf scan, G2 = post*(Lf + 0.25*e2). Stores g_pre_out, g_G2.
//  blocks 28..43 : (b, i-tile): pre_in scan of x. Stores g_pre_in.
//  blocks 44..47 : zero d_out.
// ---------------------------------------------------------------------------
__global__ void __launch_bounds__(1024) k_traces(
        const float* __restrict__ v, const float* __restrict__ z,
        const float* __restrict__ x, const float* __restrict__ e1,
        const float* __restrict__ e2, const float* __restrict__ w_out,
        float* __restrict__ out) {
    __shared__ float s_a[32][33];
    __shared__ float s_b[32][33];
    __shared__ float s_e1[TDIM * KDIM];   // 12KB
    __shared__ float s_w[32 * KDIM];

    const int tid  = threadIdx.x;
    const int lane = tid & 31;
    const int wrp  = tid >> 5;
    const int tt   = tid >> 5;   // coop-tile row (t)
    const int nn   = tid & 31;   // coop-tile col (n or i)
    const int bx   = blockIdx.x;

    if (bx < 28) {
        const int b  = bx / 7;
        const int nt = bx % 7;
        const int n0 = nt * 32;

        // preload e1[b] and w_out slice
        for (int i = tid; i < TDIM * KDIM; i += 1024)
            s_e1[i] = e1[b * TDIM * KDIM + i];
        if (tid < 32 * KDIM) {
            int n = n0 + tid / KDIM;
            s_w[tid] = (n < NDIM) ? w_out[n * KDIM + tid % KDIM] : 0.f;
        }

        const int  n_w     = n0 + wrp;               // this warp's post-neuron
        const bool valid_n = (n_w < NDIM);
        const float c2     = valid_n ? 0.25f * e2[n_w] : 0.f;  // REG/(B*T)
        const float dl     = dpow_lane(lane);
        const float dl1    = dl * D1;                 // d^(lane+1)
        const float drl    = D32 / dl;                // d^(32-lane)

        float postr[NCHUNK], Lr[NCHUNK];
        unsigned pm = 0u;          // prev chunk spike ballot
        float fcarry = 0.f;        // forward scan carry
        __syncthreads();

        // ----- phase 1: forward -----
        #pragma unroll
        for (int c = 0; c < NCHUNK; c++) {
            const int  t_ld = c * 32 + tt;
            const int  n_ld = n0 + nn;
            const bool ok   = (t_ld < TDIM) && (n_ld < NDIM);
            const int  off  = (b * TDIM + t_ld) * NDIM + n_ld;
            s_a[tt][nn] = ok ? z[off] : 0.f;
            s_b[tt][nn] = ok ? v[off] : 0.6f;
            __syncthreads();

            const float zt = s_a[lane][wrp];
            const float vt = s_b[lane][wrp];

            // refractory: any spike in z[t-1..t-4]
            const unsigned m = __ballot_sync(0xffffffffu, zt > 0.f);
            const unsigned long long w64 =
                ((unsigned long long)m << 32) | (unsigned long long)pm;
            const bool refract = ((w64 >> (28 + lane)) & 0xFull) != 0ull;
            pm = m;

            const float vs  = (vt - 0.6f) * (1.0f / 0.6f);
            const float psi = 0.5f * fmaxf(1.0f - fabsf(vs), 0.0f);
            postr[c] = refract ? 0.f : psi;

            // forward weighted scan: pre_out
            float a = zt, tmp;
            tmp = __shfl_up_sync(0xffffffffu, a, 1);  if (lane >= 1)  a = fmaf(tmp, D1,  a);
            tmp = __shfl_up_sync(0xffffffffu, a, 2);  if (lane >= 2)  a = fmaf(tmp, D2,  a);
            tmp = __shfl_up_sync(0xffffffffu, a, 4);  if (lane >= 4)  a = fmaf(tmp, D4,  a);
            tmp = __shfl_up_sync(0xffffffffu, a, 8);  if (lane >= 8)  a = fmaf(tmp, D8,  a);
            tmp = __shfl_up_sync(0xffffffffu, a, 16); if (lane >= 16) a = fmaf(tmp, D16, a);
            a = fmaf(fcarry, dl1, a);
            fcarry = __shfl_sync(0xffffffffu, a, 31);

            // learning signal L[b,t,n] = e1[b,t,:]·w_out[n,:]
            const int tg = c * 32 + lane;
            const int te = (tg < TDIM) ? tg : (TDIM - 1);
            float Ls = 0.f;
            #pragma unroll
            for (int k = 0; k < KDIM; k++)
                Ls = fmaf(s_e1[te * KDIM + k], s_w[wrp * KDIM + k], Ls);
            Lr[c] = (tg < TDIM) ? Ls : 0.f;

            // stage + coalesced store of pre_out
            __syncthreads();
            s_b[lane][wrp] = a;
            __syncthreads();
            if (ok) g_pre_out[off] = s_b[tt][nn];
        }

        // ----- phase 2: reverse Lf scan + G2 -----
        float rcarry = 0.f;
        #pragma unroll
        for (int c = NCHUNK - 1; c >= 0; c--) {
            float a = Lr[c], tmp;
            tmp = __shfl_down_sync(0xffffffffu, a, 1);  if (lane < 31) a = fmaf(tmp, D1,  a);
            tmp = __shfl_down_sync(0xffffffffu, a, 2);  if (lane < 30) a = fmaf(tmp, D2,  a);
            tmp = __shfl_down_sync(0xffffffffu, a, 4);  if (lane < 28) a = fmaf(tmp, D4,  a);
            tmp = __shfl_down_sync(0xffffffffu, a, 8);  if (lane < 24) a = fmaf(tmp, D8,  a);
            tmp = __shfl_down_sync(0xffffffffu, a, 16); if (lane < 16) a = fmaf(tmp, D16, a);
            a = fmaf(rcarry, drl, a);
            rcarry = __shfl_sync(0xffffffffu, a, 0);

            const float g2 = postr[c] * (a + c2);
            __syncthreads();
            s_a[lane][wrp] = g2;
            __syncthreads();
            const int t_st = c * 32 + tt;
            const int n_st = n0 + nn;
            if (t_st < TDIM && n_st < NDIM)
                g_G2[(b * TDIM + t_st) * NDIM + n_st] = s_a[tt][nn];
        }
    } else if (bx < 44) {
        // input traces pre_in
        const int idx = bx - 28;
        const int b   = idx >> 2;
        const int i0  = (idx & 3) * 32;
        float fcarry = 0.f;
        const float dl1 = dpow_lane(lane) * D1;
        __syncthreads();
        #pragma unroll
        for (int c = 0; c < NCHUNK; c++) {
            const int  t_ld = c * 32 + tt;
            const int  i_ld = i0 + nn;
            const bool ok   = (t_ld < TDIM) && (i_ld < NIN);
            const int  off  = (b * TDIM + t_ld) * NIN + i_ld;
            s_a[tt][nn] = ok ? x[off] : 0.f;
            __syncthreads();
            float a = s_a[lane][wrp], tmp;
            tmp = __shfl_up_sync(0xffffffffu, a, 1);  if (lane >= 1)  a = fmaf(tmp, D1,  a);
            tmp = __shfl_up_sync(0xffffffffu, a, 2);  if (lane >= 2)  a = fmaf(tmp, D2,  a);
            tmp = __shfl_up_sync(0xffffffffu, a, 4);  if (lane >= 4)  a = fmaf(tmp, D4,  a);
            tmp = __shfl_up_sync(0xffffffffu, a, 8);  if (lane >= 8)  a = fmaf(tmp, D8,  a);
            tmp = __shfl_up_sync(0xffffffffu, a, 16); if (lane >= 16) a = fmaf(tmp, D16, a);
            a = fmaf(fcarry, dl1, a);
            fcarry = __shfl_sync(0xffffffffu, a, 31);
            __syncthreads();
            s_a[lane][wrp] = a;
            __syncthreads();
            if (ok) g_pre_in[off] = s_a[tt][nn];
        }
    } else {
        // zero the output (atomics accumulate into it in k_gemm)
        for (int i = (bx - 44) * 1024 + tid; i < OUT_TOTAL; i += 4 * 1024)
            out[i] = 0.f;
    }
}

// ---------------------------------------------------------------------------
// Kernel 2: split-K GEMMs, atomicAdd into zeroed output.
//   tiles 0..69 : [pre_in; pre_rec]^T (M=300) x G2 (N=200)
//                 (pre_rec read as shifted pre_out)
//   tiles 70..76: pre_out^T (M=200) x error1 (N=10)
//   blockIdx.y = K-chunk of 100: b = y/3, t0 = (y%3)*100
// ---------------------------------------------------------------------------
__global__ void __launch_bounds__(256) k_gemm(const float* __restrict__ e1,
                                              float* __restrict__ out) {
    __shared__ float As[32][33];
    __shared__ float Bs[32][33];

    const int chunk = blockIdx.y;
    const int b  = chunk / 3;
    const int t0 = (chunk % 3) * 100;
    const int tile = blockIdx.x;
    const int tid = threadIdx.x;
    const bool is_main = (tile < 70);

    int m0, n0;
    if (is_main) { m0 = (tile / 7) * 32; n0 = (tile % 7) * 32; }
    else         { m0 = (tile - 70) * 32; n0 = 0; }

    const int baseBT = b * TDIM + t0;

    float acc00 = 0.f, acc01 = 0.f, acc10 = 0.f, acc11 = 0.f;
    const int ty = tid >> 4, tx = tid & 15;

    for (int ks = 0; ks < 100; ks += 32) {
        #pragma unroll
        for (int r = 0; r < 4; r++) {
            int e  = tid + r * 256;
            int kk = e >> 5;
            int mm = e & 31;
            int kidx = ks + kk;
            bool kok = (kidx < 100);
            int trow = baseBT + kidx;
            float aval = 0.f, bval = 0.f;
            if (kok) {
                if (is_main) {
                    int gm = m0 + mm;
                    if (gm < NIN) {
                        aval = g_pre_in[trow * NIN + gm];
                    } else if (gm < NIN + NDIM) {
                        int tloc = t0 + kidx;
                        if (tloc > 0)   // pre_rec[t] = pre_out[t-1], 0 at t=0
                            aval = g_pre_out[(trow - 1) * NDIM + (gm - NIN)];
                    }
                    int gn = n0 + mm;
                    if (gn < NDIM) bval = g_G2[trow * NDIM + gn];
                } else {
                    int gm = m0 + mm;
                    if (gm < NDIM) aval = g_pre_out[trow * NDIM + gm];
                    if (mm < KDIM) bval = e1[trow * KDIM + mm];
                }
            }
            As[kk][mm] = aval;
            Bs[kk][mm] = bval;
        }
        __syncthreads();
        #pragma unroll
        for (int kk = 0; kk < 32; kk++) {
            float a0 = As[kk][2 * ty], a1 = As[kk][2 * ty + 1];
            float b0 = Bs[kk][2 * tx], b1 = Bs[kk][2 * tx + 1];
            acc00 = fmaf(a0, b0, acc00);
            acc01 = fmaf(a0, b1, acc01);
            acc10 = fmaf(a1, b0, acc10);
            acc11 = fmaf(a1, b1, acc11);
        }
        __syncthreads();
    }

    float accs[2][2] = {{acc00, acc01}, {acc10, acc11}};
    #pragma unroll
    for (int i = 0; i < 2; i++) {
        #pragma unroll
        for (int j = 0; j < 2; j++) {
            int gm = m0 + 2 * ty + i;
            int gn = n0 + 2 * tx + j;
            float val = accs[i][j];
            if (is_main) {
                if (gn < NDIM) {
                    if (gm < NIN) {
                        atomicAdd(&out[gm * NDIM + gn], val);
                    } else if (gm < NIN + NDIM) {
                        int rr = gm - NIN;
                        if (rr != gn)   // autapse mask: diagonal stays 0
                            atomicAdd(&out[NIN * NDIM + rr * NDIM + gn], val);
                    }
                }
            } else {
                if (gm < NDIM && gn < KDIM)
                    atomicAdd(&out[NIN * NDIM + NDIM * NDIM + gm * KDIM + gn], val);
            }
        }
    }
}

extern "C" void kernel_launch(void* const* d_in, const int* in_sizes, int n_in,
                              void* d_out, int out_size) {
    const float* v     = (const float*)d_in[0];
    const float* z     = (const float*)d_in[1];
    const float* x     = (const float*)d_in[2];
    const float* e1    = (const float*)d_in[3];
    const float* e2    = (const float*)d_in[4];
    const float* w_out = (const float*)d_in[5];
    float* out = (float*)d_out;

    k_traces<<<48, 1024>>>(v, z, x, e1, e2, w_out, out);
    k_gemm<<<dim3(77, 12), 256>>>(e1, out);
}

// round 4
// speedup vs baseline: 5.0792x; 1.4189x over previous
#include <cuda_runtime.h>

#define BDIM 4
#define TDIM 300
#define NDIM 200
#define NIN  100
#define KDIM 10
#define NCHUNK 10          // ceil(300/32)

#define BTN (BDIM*TDIM*NDIM)     // 240000
#define BTI (BDIM*TDIM*NIN)      // 120000
#define OUT_TOTAL (NIN*NDIM + NDIM*NDIM + NDIM*KDIM)  // 62000

#define D1  0.8f
#define D2  0.64f
#define D4  0.4096f
#define D8  0.16777216f
#define D16 0.0281474976710656f
#define D32 0.000792281625142643f

#define NCH 12             // split-K chunks: 4 b * 3 t-chunks of 100
#define MTILES 20          // 5 m-tiles x 4 n-tiles of 64x64
#define OTILES 4           // dw_out m-tiles of 64x16

// scratch (device globals — no cudaMalloc allowed)
__device__ __align__(16) float g_pre_out[BTN];
__device__ __align__(16) float g_pre_in[BTI];
__device__ __align__(16) float g_G2[BTN];
__device__ __align__(16) float g_partM[NCH * MTILES * 64 * 64];  // 983040
__device__ __align__(16) float g_partO[NCH * OTILES * 64 * 16];  // 49152

typedef unsigned long long ull;

__device__ __forceinline__ ull pk(float x, float y) {
    ull r;
    asm("mov.b64 %0, {%1, %2};" : "=l"(r)
        : "r"(__float_as_uint(x)), "r"(__float_as_uint(y)));
    return r;
}
__device__ __forceinline__ void fma2(ull& d, ull a, ull b) {
    asm("fma.rn.f32x2 %0, %1, %2, %3;" : "=l"(d) : "l"(a), "l"(b), "l"(d));
}
__device__ __forceinline__ float2 upk(ull v) {
    unsigned lo, hi;
    asm("mov.b64 {%0, %1}, %2;" : "=r"(lo), "=r"(hi) : "l"(v));
    float2 f;
    f.x = __uint_as_float(lo);
    f.y = __uint_as_float(hi);
    return f;
}

__device__ __forceinline__ float dpow_lane(int l) {
    float p = 1.f;
    if (l & 1)  p *= D1;
    if (l & 2)  p *= D2;
    if (l & 4)  p *= D4;
    if (l & 8)  p *= D8;
    if (l & 16) p *= D16;
    return p;
}

__device__ __forceinline__ float warp_fscan(float a, int lane) {
    float tmp;
    tmp = __shfl_up_sync(0xffffffffu, a, 1);  if (lane >= 1)  a = fmaf(tmp, D1,  a);
    tmp = __shfl_up_sync(0xffffffffu, a, 2);  if (lane >= 2)  a = fmaf(tmp, D2,  a);
    tmp = __shfl_up_sync(0xffffffffu, a, 4);  if (lane >= 4)  a = fmaf(tmp, D4,  a);
    tmp = __shfl_up_sync(0xffffffffu, a, 8);  if (lane >= 8)  a = fmaf(tmp, D8,  a);
    tmp = __shfl_up_sync(0xffffffffu, a, 16); if (lane >= 16) a = fmaf(tmp, D16, a);
    return a;
}
__device__ __forceinline__ float warp_rscan(float a, int lane) {
    float tmp;
    tmp = __shfl_down_sync(0xffffffffu, a, 1);  if (lane < 31) a = fmaf(tmp, D1,  a);
    tmp = __shfl_down_sync(0xffffffffu, a, 2);  if (lane < 30) a = fmaf(tmp, D2,  a);
    tmp = __shfl_down_sync(0xffffffffu, a, 4);  if (lane < 28) a = fmaf(tmp, D4,  a);
    tmp = __shfl_down_sync(0xffffffffu, a, 8);  if (lane < 24) a = fmaf(tmp, D8,  a);
    tmp = __shfl_down_sync(0xffffffffu, a, 16); if (lane < 16) a = fmaf(tmp, D16, a);
    return a;
}

// ---------------------------------------------------------------------------
// Kernel 1: fused traces. 512 threads, 16 lanes of neurons/inputs per block.
//  blocks  0..51 : (b, 16-neuron tile): post (ballot window), pre_out scan,
//                  L gemv, reverse Lf scan, G2. Prefetched, 2-group staging.
//  blocks 52..79 : (b, 16-input tile): pre_in scan of x.
// ---------------------------------------------------------------------------
__global__ void __launch_bounds__(512) k_traces(
        const float* __restrict__ v, const float* __restrict__ z,
        const float* __restrict__ x, const float* __restrict__ e1,
        const float* __restrict__ e2, const float* __restrict__ w_out) {
    __shared__ float s_z[160][17];          // 5 chunks of 32 t x 16 lanes
    __shared__ float s_v[160][17];
    __shared__ float s_e1[TDIM * KDIM];     // 12000B
    __shared__ float s_w[16 * KDIM];

    const int tid  = threadIdx.x;
    const int lane = tid & 31;
    const int wrp  = tid >> 5;     // 0..15  (owns one neuron/input)
    const int tt   = tid >> 4;     // 0..31  (t within chunk, load layout)
    const int nn   = tid & 15;     // 0..15  (lane col, load layout)
    const int bx   = blockIdx.x;

    const float dl  = dpow_lane(lane);
    const float dl1 = dl * D1;     // d^(lane+1)
    const float drl = D32 / dl;    // d^(32-lane)

    if (bx < 52) {
        const int b  = bx / 13;
        const int n0 = (bx % 13) * 16;

        for (int i = tid; i < TDIM * KDIM; i += 512)
            s_e1[i] = e1[b * TDIM * KDIM + i];
        if (tid < 16 * KDIM) {
            int n = n0 + tid / KDIM;
            s_w[tid] = (n < NDIM) ? w_out[n * KDIM + tid % KDIM] : 0.f;
        }

        const int  n_w = n0 + wrp;
        const float c2 = (n_w < NDIM) ? 0.25f * e2[n_w] : 0.f;  // REG/(B*T)

        // prefetch all chunks (load layout)
        float zr[NCHUNK], vr[NCHUNK];
        const int n_ld = n0 + nn;
        #pragma unroll
        for (int c = 0; c < NCHUNK; c++) {
            int t_ld = c * 32 + tt;
            bool ok = (t_ld < TDIM) && (n_ld < NDIM);
            int off = (b * TDIM + t_ld) * NDIM + n_ld;
            zr[c] = ok ? z[off] : 0.f;
            vr[c] = ok ? v[off] : 0.6f;
        }

        float postr[NCHUNK], Lr[NCHUNK], ar[NCHUNK];
        unsigned pm = 0u;
        float fcarry = 0.f;

        #pragma unroll
        for (int g = 0; g < 2; g++) {           // two groups of 5 chunks
            __syncthreads();                    // buffers free
            #pragma unroll
            for (int c = 0; c < 5; c++) {
                s_z[c * 32 + tt][nn] = zr[g * 5 + c];
                s_v[c * 32 + tt][nn] = vr[g * 5 + c];
            }
            __syncthreads();
            #pragma unroll
            for (int cc = 0; cc < 5; cc++) {
                const int c = g * 5 + cc;
                const float zt = s_z[cc * 32 + lane][wrp];
                const float vt = s_v[cc * 32 + lane][wrp];

                // refractory: any spike in z[t-1..t-4]
                const unsigned m = __ballot_sync(0xffffffffu, zt > 0.f);
                const ull w64 = ((ull)m << 32) | (ull)pm;
                const bool refract = ((w64 >> (28 + lane)) & 0xFull) != 0ull;
                pm = m;

                const float vs  = (vt - 0.6f) * (1.0f / 0.6f);
                postr[c] = refract ? 0.f : 0.5f * fmaxf(1.0f - fabsf(vs), 0.0f);

                float a = warp_fscan(zt, lane);
                a = fmaf(fcarry, dl1, a);
                fcarry = __shfl_sync(0xffffffffu, a, 31);
                ar[c] = a;

                const int tg = c * 32 + lane;
                const int te = (tg < TDIM) ? tg : (TDIM - 1);
                float Ls = 0.f;
                #pragma unroll
                for (int k = 0; k < KDIM; k++)
                    Ls = fmaf(s_e1[te * KDIM + k], s_w[wrp * KDIM + k], Ls);
                Lr[c] = (tg < TDIM) ? Ls : 0.f;
            }
        }

        // reverse Lf scan (registers only) -> G2 in postr slot
        float rcarry = 0.f;
        #pragma unroll
        for (int c = NCHUNK - 1; c >= 0; c--) {
            float a = warp_rscan(Lr[c], lane);
            a = fmaf(rcarry, drl, a);
            rcarry = __shfl_sync(0xffffffffu, a, 0);
            postr[c] = postr[c] * (a + c2);     // G2
        }

        // stage + coalesced store, two groups
        #pragma unroll
        for (int g = 0; g < 2; g++) {
            __syncthreads();
            #pragma unroll
            for (int cc = 0; cc < 5; cc++) {
                s_z[cc * 32 + lane][wrp] = ar[g * 5 + cc];
                s_v[cc * 32 + lane][wrp] = postr[g * 5 + cc];
            }
            __syncthreads();
            #pragma unroll
            for (int cc = 0; cc < 5; cc++) {
                int t_st = (g * 5 + cc) * 32 + tt;
                if (t_st < TDIM && n_ld < NDIM) {
                    int off = (b * TDIM + t_st) * NDIM + n_ld;
                    g_pre_out[off] = s_z[cc * 32 + tt][nn];
                    g_G2[off]      = s_v[cc * 32 + tt][nn];
                }
            }
        }
    } else {
        // ---- input traces pre_in ----
        const int idx = bx - 52;
        const int b   = idx / 7;
        const int i0  = (idx % 7) * 16;
        const int i_ld = i0 + nn;

        float xr[NCHUNK];
        #pragma unroll
        for (int c = 0; c < NCHUNK; c++) {
            int t_ld = c * 32 + tt;
            bool ok = (t_ld < TDIM) && (i_ld < NIN);
            xr[c] = ok ? x[(b * TDIM + t_ld) * NIN + i_ld] : 0.f;
        }

        float ar[NCHUNK];
        float fcarry = 0.f;
        #pragma unroll
        for (int g = 0; g < 2; g++) {
            __syncthreads();
            #pragma unroll
            for (int c = 0; c < 5; c++)
                s_z[c * 32 + tt][nn] = xr[g * 5 + c];
            __syncthreads();
            #pragma unroll
            for (int cc = 0; cc < 5; cc++) {
                float a = warp_fscan(s_z[cc * 32 + lane][wrp], lane);
                a = fmaf(fcarry, dl1, a);
                fcarry = __shfl_sync(0xffffffffu, a, 31);
                ar[g * 5 + cc] = a;
            }
        }
        #pragma unroll
        for (int g = 0; g < 2; g++) {
            __syncthreads();
            #pragma unroll
            for (int cc = 0; cc < 5; cc++)
                s_z[cc * 32 + lane][wrp] = ar[g * 5 + cc];
            __syncthreads();
            #pragma unroll
            for (int cc = 0; cc < 5; cc++) {
                int t_st = (g * 5 + cc) * 32 + tt;
                if (t_st < TDIM && i_ld < NIN)
                    g_pre_in[(b * TDIM + t_st) * NIN + i_ld] = s_z[cc * 32 + tt][nn];
            }
        }
    }
}

// ---------------------------------------------------------------------------
// Kernel 2: split-K GEMMs -> private scratch (no atomics).
//  grid (24, 12): x<20 main 64x64 tiles of [pre_in;pre_rec]^T x G2,
//                 x>=20 dw_out 64x16 tiles of pre_out^T x e1.
//  y = K-chunk: b = y/3, t0 = (y%3)*100.
// ---------------------------------------------------------------------------
#define KSTEP 20
__global__ void __launch_bounds__(256) k_gemm(const float* __restrict__ e1) {
    __shared__ float As[KSTEP][68];
    __shared__ float Bs[KSTEP][68];

    const int chunk = blockIdx.y;
    const int b  = chunk / 3;
    const int t0 = (chunk % 3) * 100;
    const int tile = blockIdx.x;
    const int tid  = threadIdx.x;
    const int ty = tid >> 4, tx = tid & 15;
    const int bt0 = b * TDIM + t0;

    if (tile < MTILES) {
        const int m0 = (tile / 4) * 64;
        const int n0 = (tile % 4) * 64;

        ull acc[4][2];
        #pragma unroll
        for (int i = 0; i < 4; i++) { acc[i][0] = 0ull; acc[i][1] = 0ull; }

        for (int ks = 0; ks < 100; ks += KSTEP) {
            #pragma unroll
            for (int r = 0; r < 5; r++) {
                int idx = tid + r * 256;
                int kk = idx >> 6, mm = idx & 63;
                int t_local = t0 + ks + kk;
                int trow = b * TDIM + t_local;
                int gm = m0 + mm;
                float a;
                if (gm < NIN) {
                    a = g_pre_in[trow * NIN + gm];
                } else {
                    a = (t_local > 0) ? g_pre_out[(trow - 1) * NDIM + (gm - NIN)] : 0.f;
                }
                As[kk][mm] = a;
                int gn = n0 + mm;
                Bs[kk][mm] = (gn < NDIM) ? g_G2[trow * NDIM + gn] : 0.f;
            }
            __syncthreads();
            #pragma unroll
            for (int kk = 0; kk < KSTEP; kk++) {
                float4 av = *(const float4*)&As[kk][ty * 4];
                float4 bv = *(const float4*)&Bs[kk][tx * 4];
                ull b01 = pk(bv.x, bv.y);
                ull b23 = pk(bv.z, bv.w);
                ull aa;
                aa = pk(av.x, av.x); fma2(acc[0][0], aa, b01); fma2(acc[0][1], aa, b23);
                aa = pk(av.y, av.y); fma2(acc[1][0], aa, b01); fma2(acc[1][1], aa, b23);
                aa = pk(av.z, av.z); fma2(acc[2][0], aa, b01); fma2(acc[2][1], aa, b23);
                aa = pk(av.w, av.w); fma2(acc[3][0], aa, b01); fma2(acc[3][1], aa, b23);
            }
            __syncthreads();
        }

        const int base = (chunk * MTILES + tile) * 4096;
        #pragma unroll
        for (int i = 0; i < 4; i++) {
            float2 p0 = upk(acc[i][0]);
            float2 p1 = upk(acc[i][1]);
            float4 o = make_float4(p0.x, p0.y, p1.x, p1.y);
            *(float4*)&g_partM[base + (ty * 4 + i) * 64 + tx * 4] = o;
        }
    } else {
        // dw_out tile: 64 m-rows x 16 (10 valid) cols
        const int tm = tile - MTILES;
        const int m0 = tm * 64;
        float acc[4] = {0.f, 0.f, 0.f, 0.f};

        for (int ks = 0; ks < 100; ks += KSTEP) {
            #pragma unroll
            for (int r = 0; r < 5; r++) {
                int idx = tid + r * 256;
                int kk = idx >> 6, mm = idx & 63;
                int trow = bt0 + ks + kk;
                int gm = m0 + mm;
                As[kk][mm] = (gm < NDIM) ? g_pre_out[trow * NDIM + gm] : 0.f;
            }
            // FIX (R3 bug): KSTEP*16 = 320 > 256 threads, so stride the load.
            for (int idx = tid; idx < KSTEP * 16; idx += 256) {
                int kk = idx >> 4, kc = idx & 15;
                Bs[kk][kc] = (kc < KDIM) ? e1[(bt0 + ks + kk) * KDIM + kc] : 0.f;
            }
            __syncthreads();
            #pragma unroll
            for (int kk = 0; kk < KSTEP; kk++) {
                float4 av = *(const float4*)&As[kk][ty * 4];
                float bb = Bs[kk][tx];
                acc[0] = fmaf(av.x, bb, acc[0]);
                acc[1] = fmaf(av.y, bb, acc[1]);
                acc[2] = fmaf(av.z, bb, acc[2]);
                acc[3] = fmaf(av.w, bb, acc[3]);
            }
            __syncthreads();
        }

        const int base = (chunk * OTILES + tm) * 1024;
        #pragma unroll
        for (int i = 0; i < 4; i++)
            g_partO[base + (ty * 4 + i) * 16 + tx] = acc[i];
    }
}

// ---------------------------------------------------------------------------
// Kernel 3: reduce 12 split-K partials per output element, diagonal mask.
// ---------------------------------------------------------------------------
__global__ void __launch_bounds__(512) k_reduce(float* __restrict__ out) {
    const int o = blockIdx.x * 512 + threadIdx.x;
    if (o >= OUT_TOTAL) return;
    float s = 0.f;
    if (o < NIN * NDIM + NDIM * NDIM) {
        int mrow, n;
        bool is_rec = (o >= NIN * NDIM);
        if (!is_rec) { mrow = o / NDIM;                 n = o % NDIM; }
        else         { int p = o - NIN * NDIM;
                       mrow = NIN + p / NDIM;           n = p % NDIM; }
        const int tidx  = (mrow >> 6) * 4 + (n >> 6);
        const int local = (mrow & 63) * 64 + (n & 63);
        #pragma unroll
        for (int c = 0; c < NCH; c++)
            s += g_partM[(c * MTILES + tidx) * 4096 + local];
        if (is_rec && (mrow - NIN) == n) s = 0.f;   // autapse mask
        out[o] = s;
    } else {
        int p = o - (NIN * NDIM + NDIM * NDIM);
        int m = p / KDIM, k = p % KDIM;
        const int local = (m & 63) * 16 + k;
        const int tm = m >> 6;
        #pragma unroll
        for (int c = 0; c < NCH; c++)
            s += g_partO[(c * OTILES + tm) * 1024 + local];
        out[o] = s;
    }
}

extern "C" void kernel_launch(void* const* d_in, const int* in_sizes, int n_in,
                              void* d_out, int out_size) {
    const float* v     = (const float*)d_in[0];
    const float* z     = (const float*)d_in[1];
    const float* x     = (const float*)d_in[2];
    const float* e1    = (const float*)d_in[3];
    const float* e2    = (const float*)d_in[4];
    const float* w_out = (const float*)d_in[5];
    float* out = (float*)d_out;

    k_traces<<<80, 512>>>(v, z, x, e1, e2, w_out);
    k_gemm<<<dim3(24, 12), 256>>>(e1);
    k_reduce<<<(OUT_TOTAL + 511) / 512, 512>>>(out);
}